// round 2
// baseline (speedup 1.0000x reference)
#include <cuda_runtime.h>
#include <cstdint>

#define VOCAB 67
#define EMB 50
#define NLAYERS 8
#define NGROUPS 131072        // (64*8192)/4 tokens per group
#define REP_FLOATS 4824       // 67 rows * 72 floats
#define REP_BYTES  19296
#define TAB_FLOATS (4*REP_FLOATS)
#define TAB_BYTES  (4*REP_BYTES)

// Precomputed per-token logits, stored as 4 shifted replicas:
// replica j stores row element e at position e + ((4-j)&3), rows padded to 72 floats.
__device__ float g_tab[TAB_FLOATS];

// ---------------------------------------------------------------------------
// Kernel 1: compute logits for all 67 vocab tokens (tiny).
// Block t handles token t. Threads 0-63 -> real part, 64-127 -> imag part.
// ---------------------------------------------------------------------------
__global__ void __launch_bounds__(128) table_kernel(
    const float* __restrict__ emb,   // [67,50]
    const float* __restrict__ kappa, // [8,50,50]
    const float* __restrict__ phi,   // [8,50,50]
    const float* __restrict__ W_out, // [50,67]
    const float* __restrict__ b_out) // [67]
{
    const int t   = blockIdx.x;
    const int tid = threadIdx.x;
    const int part = tid >> 6;   // 0 = real, 1 = imag
    const int f    = tid & 63;

    __shared__ float sar[2][EMB], sai[2][EMB], sint[EMB];

    if (tid < EMB) { sar[0][tid] = emb[t*EMB + tid]; sai[0][tid] = 0.f; }
    __syncthreads();

    for (int l = 0; l < NLAYERS; ++l) {
        const int cur = l & 1, nxt = cur ^ 1;
        if (f < EMB) {
            const float* K = kappa + l*EMB*EMB;
            const float* P = phi   + l*EMB*EMB;
            float acc = 0.f;
            if (part == 0) {
                #pragma unroll
                for (int e = 0; e < EMB; ++e) {
                    float kv = __ldg(K + e*EMB + f);
                    float pv = __ldg(P + e*EMB + f);
                    acc += sar[cur][e]*kv - sai[cur][e]*pv;
                }
                sar[nxt][f] = acc;
            } else {
                #pragma unroll
                for (int e = 0; e < EMB; ++e) {
                    float kv = __ldg(K + e*EMB + f);
                    float pv = __ldg(P + e*EMB + f);
                    acc += sar[cur][e]*pv + sai[cur][e]*kv;
                }
                sai[nxt][f] = acc;
            }
        }
        __syncthreads();
    }
    // after 8 layers the result sits in buffer index 0
    if (tid < EMB) {
        float a = sar[0][tid], b = sai[0][tid];
        sint[tid] = a*a + b*b;
    }
    __syncthreads();
    if (tid < VOCAB) {
        float acc = __ldg(b_out + tid);
        #pragma unroll
        for (int e = 0; e < EMB; ++e)
            acc += sint[e] * __ldg(W_out + e*VOCAB + tid);
        // write the 4 shifted replicas (pads: j=0->0, 1->3, 2->2, 3->1)
        g_tab[0*REP_FLOATS + t*72 + tid + 0] = acc;
        g_tab[1*REP_FLOATS + t*72 + tid + 3] = acc;
        g_tab[2*REP_FLOATS + t*72 + tid + 2] = acc;
        g_tab[3*REP_FLOATS + t*72 + tid + 1] = acc;
    }
}

// ---------------------------------------------------------------------------
// Shared-memory load helpers (guaranteed LDS in SASS).
// ---------------------------------------------------------------------------
__device__ __forceinline__ float4 lds128(uint32_t a) {
    float4 v;
    asm("ld.shared.v4.f32 {%0,%1,%2,%3}, [%4];"
        : "=f"(v.x), "=f"(v.y), "=f"(v.z), "=f"(v.w) : "r"(a));
    return v;
}
__device__ __forceinline__ float2 lds64(uint32_t a) {
    float2 v;
    asm("ld.shared.v2.f32 {%0,%1}, [%2];" : "=f"(v.x), "=f"(v.y) : "r"(a));
    return v;
}

// ---------------------------------------------------------------------------
// Kernel 2: gather. 4 tokens per group = 1072B = 67 aligned float4s.
// 4 lanes cooperate per group (lane&3 = quad phase), so lanes 0..3 store
// 64B contiguous per step. Table read from smem via 4 shifted replicas so
// every quad is ONE aligned LDS.128 (plus 3 boundary fixups per group).
// ---------------------------------------------------------------------------
__global__ void __launch_bounds__(256) gather_kernel(
    const int* __restrict__ idx, float* __restrict__ out)
{
    extern __shared__ float smem[];

    // stage the replicated table into shared
    {
        const float4* src = (const float4*)g_tab;
        float4* dst = (float4*)smem;
        for (int i = threadIdx.x; i < TAB_FLOATS/4; i += 256) dst[i] = src[i];
    }
    __syncthreads();

    const uint32_t sb = (uint32_t)__cvta_generic_to_shared(smem);
    const int lane = threadIdx.x & 31;
    const int la3  = lane & 3;
    const int lg   = lane >> 2;
    const int la16 = la3 * 16;
    const int warp  = (blockIdx.x * 256 + (int)threadIdx.x) >> 5;
    const int nwarp = (gridDim.x * 256) >> 5;

    // D_j = -268*j + 4*pad_j folded into base so LDS offset is 64*m for all lanes
    const uint32_t S0 = sb + 0*REP_BYTES + la16 + 0;
    const uint32_t S1 = sb + 1*REP_BYTES + la16 - 256;
    const uint32_t S2 = sb + 2*REP_BYTES + la16 - 528;
    const uint32_t S3 = sb + 3*REP_BYTES + la16 - 800;

    for (int gbase = warp * 8; gbase < NGROUPS; gbase += nwarp * 8) {
        const int g = gbase + lg;
        const int4 tk = __ldg((const int4*)(idx + 4*g));
        const uint32_t B0 = S0 + (uint32_t)tk.x * 288;
        const uint32_t B1 = S1 + (uint32_t)tk.y * 288;
        const uint32_t B2 = S2 + (uint32_t)tk.z * 288;
        const uint32_t B3 = S3 + (uint32_t)tk.w * 288;
        float* O = out + (uint32_t)g * 268 + la3 * 4;

        #pragma unroll
        for (int m = 0; m < 17; ++m) {
            const int q = 4*m + la3;   // global quad index within the group
            const uint32_t B = (q < 17) ? B0 : (q < 34) ? B1 : (q < 51) ? B2 : B3;
            float4 v = lds128(B + 64*m);

            if (m == 4 && la3 == 0) {            // q=16: elems {t0:64,65,66 | t1:0}
                float4 p = lds128(B1 + 256);     // rep1 row t1 bytes 0..15 = {pad,pad,pad,e0}
                v.w = p.w;
            }
            if (m == 8 && la3 == 1) {            // q=33: {t1:65,66 | t2:0,1}
                float2 p = lds64(B2 + 520);      // rep2 row t2 bytes 8..15 = {e0,e1}
                v.z = p.x; v.w = p.y;
            }
            if (m == 12 && la3 == 2) {           // q=50: {t2:66 | t3:0,1,2}
                float4 p = lds128(B3 + 768);     // rep3 row t3 bytes 0..15 = {pad,e0,e1,e2}
                v.y = p.y; v.z = p.z; v.w = p.w;
            }
            if (!(m == 16 && la3 == 3))          // quad 67 doesn't exist
                *(float4*)(O + 16*m) = v;
        }
    }
}

// ---------------------------------------------------------------------------
// Launch
// ---------------------------------------------------------------------------
extern "C" void kernel_launch(void* const* d_in, const int* in_sizes, int n_in,
                              void* d_out, int out_size) {
    const int*   idx = (const int*)d_in[0];   // input_seq [64,8192] int32
    const float* emb = (const float*)d_in[1]; // embedding_table [67,50]
    const float* kap = (const float*)d_in[2]; // kappa [8,50,50]
    const float* ph  = (const float*)d_in[3]; // phi   [8,50,50]
    const float* Wo  = (const float*)d_in[4]; // W_out [50,67]
    const float* bo  = (const float*)d_in[5]; // b_out [67]
    float* out = (float*)d_out;

    // 77 KB dynamic smem needs the opt-in (idempotent; safe to repeat).
    cudaFuncSetAttribute(gather_kernel,
                         cudaFuncAttributeMaxDynamicSharedMemorySize, TAB_BYTES);

    table_kernel<<<VOCAB, 128>>>(emb, kap, ph, Wo, bo);
    gather_kernel<<<304, 256, TAB_BYTES>>>(idx, out);
}

// round 3
// speedup vs baseline: 2.0501x; 2.0501x over previous
#include <cuda_runtime.h>
#include <cstdint>

#define VOCAB 67
#define EMB 50
#define NLAYERS 8
#define NGROUPS 131072        // (64*8192)/4 tokens per group
#define REP_FLOATS 4824       // 67 rows * 72 floats
#define TAB_FLOATS (4*REP_FLOATS)

// Precomputed per-token logits, stored as 4 shifted replicas:
// replica j stores row element e at position e + pad_j (pads 0,3,2,1), rows padded to 72 floats.
__device__ __align__(16) float g_tab[TAB_FLOATS];

// ---------------------------------------------------------------------------
// Kernel 1: compute logits for all 67 vocab tokens.
// Block t handles token t. Per layer: cooperatively stage K_l/P_l into smem
// (pipelined float4 loads), then threads 0-49 compute real, 64-113 imag.
// ---------------------------------------------------------------------------
__global__ void __launch_bounds__(128) table_kernel(
    const float* __restrict__ emb,   // [67,50]
    const float* __restrict__ kappa, // [8,50,50]
    const float* __restrict__ phi,   // [8,50,50]
    const float* __restrict__ W_out, // [50,67]
    const float* __restrict__ b_out) // [67]
{
    const int t   = blockIdx.x;
    const int tid = threadIdx.x;

    __shared__ float wK[EMB*EMB], wP[EMB*EMB];       // 20 KB
    __shared__ float sar[2][EMB], sai[2][EMB], sint[EMB];

    if (tid < EMB) { sar[0][tid] = emb[t*EMB + tid]; sai[0][tid] = 0.f; }

    for (int l = 0; l < NLAYERS; ++l) {
        __syncthreads();
        // stage this layer's weights: 2500 floats = 625 float4 each
        const float4* K4 = (const float4*)(kappa + l*EMB*EMB);
        const float4* P4 = (const float4*)(phi   + l*EMB*EMB);
        #pragma unroll
        for (int i = 0; i < 5; ++i) {
            int j = tid + i*128;
            if (j < 625) {
                ((float4*)wK)[j] = __ldg(K4 + j);
                ((float4*)wP)[j] = __ldg(P4 + j);
            }
        }
        __syncthreads();

        const int cur = l & 1, nxt = cur ^ 1;
        if (tid < EMB) {                       // real part, f = tid
            float acc = 0.f;
            #pragma unroll
            for (int e = 0; e < EMB; ++e)
                acc += sar[cur][e]*wK[e*EMB + tid] - sai[cur][e]*wP[e*EMB + tid];
            sar[nxt][tid] = acc;
        } else if (tid >= 64 && tid < 64 + EMB) {  // imag part, f = tid-64
            const int f = tid - 64;
            float acc = 0.f;
            #pragma unroll
            for (int e = 0; e < EMB; ++e)
                acc += sar[cur][e]*wP[e*EMB + f] + sai[cur][e]*wK[e*EMB + f];
            sai[nxt][f] = acc;
        }
    }
    __syncthreads();
    // after 8 layers (even) the result sits in buffer index 0
    if (tid < EMB) {
        float a = sar[0][tid], b = sai[0][tid];
        sint[tid] = a*a + b*b;
    }
    __syncthreads();
    if (tid < VOCAB) {
        float acc = __ldg(b_out + tid);
        #pragma unroll
        for (int e = 0; e < EMB; ++e)
            acc += sint[e] * __ldg(W_out + e*VOCAB + tid);
        // write the 4 shifted replicas (pads: j=0->0, 1->3, 2->2, 3->1)
        g_tab[0*REP_FLOATS + t*72 + tid + 0] = acc;
        g_tab[1*REP_FLOATS + t*72 + tid + 3] = acc;
        g_tab[2*REP_FLOATS + t*72 + tid + 2] = acc;
        g_tab[3*REP_FLOATS + t*72 + tid + 1] = acc;
    }
}

// ---------------------------------------------------------------------------
// Kernel 2: gather. 4 tokens per group = 1072B = 67 aligned float4s.
// 4 lanes cooperate per group (lane&3 = quad phase) so lanes 0..3 store
// 64B contiguous per step. Table read straight from global via __ldg —
// the 77 KB replicated table is L1-resident, so no smem (occupancy 4x).
// ---------------------------------------------------------------------------
__device__ __forceinline__ void stcs128(float* p, float4 v) {
    asm volatile("st.global.cs.v4.f32 [%0], {%1,%2,%3,%4};"
                 :: "l"(p), "f"(v.x), "f"(v.y), "f"(v.z), "f"(v.w) : "memory");
}

__global__ void __launch_bounds__(256) gather_kernel(
    const int* __restrict__ idx, float* __restrict__ out)
{
    const int lane = threadIdx.x & 31;
    const int la3  = lane & 3;
    const int lg   = lane >> 2;
    const int la4  = la3 * 4;                       // element offset
    const int warp = (blockIdx.x * 256 + (int)threadIdx.x) >> 5;  // 0..16383

    // replica bases (element offsets), shift folded so offset is 16*m for all lanes
    const int S0 = 0*REP_FLOATS + la4 + 0;
    const int S1 = 1*REP_FLOATS + la4 - 64;
    const int S2 = 2*REP_FLOATS + la4 - 132;
    const int S3 = 3*REP_FLOATS + la4 - 200;

    const int g = warp * 8 + lg;                    // < NGROUPS always
    const int4 tk = __ldg((const int4*)(idx + 4*g));
    const int B0 = S0 + tk.x * 72;
    const int B1 = S1 + tk.y * 72;
    const int B2 = S2 + tk.z * 72;
    const int B3 = S3 + tk.w * 72;
    float* O = out + (uint32_t)g * 268 + la4;

    #pragma unroll
    for (int m = 0; m < 17; ++m) {
        const int q = 4*m + la3;   // global quad index within the group
        const int B = (q < 17) ? B0 : (q < 34) ? B1 : (q < 51) ? B2 : B3;
        float4 v = __ldg((const float4*)(g_tab + B + 16*m));

        if (m == 4 && la3 == 0) {            // q=16: elems {t0:64,65,66 | t1:0}
            float4 p = __ldg((const float4*)(g_tab + B1 + 64)); // rep1 t1 pos 0..3 = {pad,pad,pad,e0}
            v.w = p.w;
        }
        if (m == 8 && la3 == 1) {            // q=33: {t1:65,66 | t2:0,1}
            float2 p = __ldg((const float2*)(g_tab + B2 + 130)); // rep2 t2 pos 2..3 = {e0,e1}
            v.z = p.x; v.w = p.y;
        }
        if (m == 12 && la3 == 2) {           // q=50: {t2:66 | t3:0,1,2}
            float4 p = __ldg((const float4*)(g_tab + B3 + 192)); // rep3 t3 pos 0..3 = {pad,e0,e1,e2}
            v.y = p.y; v.z = p.z; v.w = p.w;
        }
        if (!(m == 16 && la3 == 3))          // quad 67 doesn't exist
            stcs128(O + 16*m, v);
    }
}

// ---------------------------------------------------------------------------
// Launch
// ---------------------------------------------------------------------------
extern "C" void kernel_launch(void* const* d_in, const int* in_sizes, int n_in,
                              void* d_out, int out_size) {
    const int*   idx = (const int*)d_in[0];   // input_seq [64,8192] int32
    const float* emb = (const float*)d_in[1]; // embedding_table [67,50]
    const float* kap = (const float*)d_in[2]; // kappa [8,50,50]
    const float* ph  = (const float*)d_in[3]; // phi   [8,50,50]
    const float* Wo  = (const float*)d_in[4]; // W_out [50,67]
    const float* bo  = (const float*)d_in[5]; // b_out [67]
    float* out = (float*)d_out;

    table_kernel<<<VOCAB, 128>>>(emb, kap, ph, Wo, bo);
    gather_kernel<<<2048, 256>>>(idx, out);   // 16384 warps = NGROUPS/8, one tile each
}

// round 4
// speedup vs baseline: 3.2318x; 1.5764x over previous
#include <cuda_runtime.h>
#include <cstdint>

#define VOCAB 67
#define EMB 50
#define NLAYERS 8
#define NWARPS 16384          // (64*8192)/32 tokens per warp
#define REP_FLOATS 4824       // 67 rows * 72 floats
#define TAB_FLOATS (4*REP_FLOATS)

// Precomputed per-token logits, stored as 4 shifted replicas:
// replica j stores row element e at padded position e + pad_j (pads 0,3,2,1), rows 72 floats.
__device__ __align__(16) float g_tab[TAB_FLOATS];

// ---------------------------------------------------------------------------
// cp.async helpers
// ---------------------------------------------------------------------------
__device__ __forceinline__ void cp16(uint32_t s, const void* g) {
    asm volatile("cp.async.cg.shared.global [%0], [%1], 16;" :: "r"(s), "l"(g));
}
__device__ __forceinline__ void cp_commit() { asm volatile("cp.async.commit_group;"); }
template<int N> __device__ __forceinline__ void cp_wait() {
    asm volatile("cp.async.wait_group %0;" :: "n"(N));
}

// ---------------------------------------------------------------------------
// Kernel 1: per-token logits table. Block t handles token t.
// Double-buffered cp.async staging of each layer's K/P; threads 0-49 real,
// 64-113 imag; 4-way split accumulators.
// ---------------------------------------------------------------------------
__global__ void __launch_bounds__(128) table_kernel(
    const float* __restrict__ emb,   // [67,50]
    const float* __restrict__ kappa, // [8,50,50]
    const float* __restrict__ phi,   // [8,50,50]
    const float* __restrict__ W_out, // [50,67]
    const float* __restrict__ b_out) // [67]
{
    const int t   = blockIdx.x;
    const int tid = threadIdx.x;

    __shared__ __align__(16) float wK[2][EMB*EMB], wP[2][EMB*EMB];  // 40 KB
    __shared__ float sar[2][EMB], sai[2][EMB], sint[EMB];

    const uint32_t sK0 = (uint32_t)__cvta_generic_to_shared(&wK[0][0]);
    const uint32_t sK1 = (uint32_t)__cvta_generic_to_shared(&wK[1][0]);
    const uint32_t sP0 = (uint32_t)__cvta_generic_to_shared(&wP[0][0]);
    const uint32_t sP1 = (uint32_t)__cvta_generic_to_shared(&wP[1][0]);

    if (tid < EMB) { sar[0][tid] = emb[t*EMB + tid]; sai[0][tid] = 0.f; }

    // prefetch layer 0 into buffer 0
    #pragma unroll
    for (int i = 0; i < 5; ++i) {
        int j = tid + i*128;
        if (j < 625) {
            cp16(sK0 + j*16, kappa + j*4);
            cp16(sP0 + j*16, phi   + j*4);
        }
    }
    cp_commit();

    for (int l = 0; l < NLAYERS; ++l) {
        const int buf = l & 1;
        // prefetch next layer into the other buffer (safe: that buffer's
        // consumer finished before the previous iteration's trailing sync)
        if (l + 1 < NLAYERS) {
            const uint32_t dK = (buf ? sK0 : sK1), dP = (buf ? sP0 : sP1);
            const float* gK = kappa + (l+1)*EMB*EMB;
            const float* gP = phi   + (l+1)*EMB*EMB;
            #pragma unroll
            for (int i = 0; i < 5; ++i) {
                int j = tid + i*128;
                if (j < 625) {
                    cp16(dK + j*16, gK + j*4);
                    cp16(dP + j*16, gP + j*4);
                }
            }
            cp_commit();
            cp_wait<1>();
        } else {
            cp_wait<0>();
        }
        __syncthreads();

        const int cur = l & 1, nxt = cur ^ 1;
        const float* K = wK[buf];
        const float* P = wP[buf];
        if (tid < EMB) {                       // real, f = tid
            float a0=0.f,a1=0.f,a2=0.f,a3=0.f;
            #pragma unroll
            for (int e = 0; e < 48; e += 4) {
                a0 += sar[cur][e+0]*K[(e+0)*EMB+tid] - sai[cur][e+0]*P[(e+0)*EMB+tid];
                a1 += sar[cur][e+1]*K[(e+1)*EMB+tid] - sai[cur][e+1]*P[(e+1)*EMB+tid];
                a2 += sar[cur][e+2]*K[(e+2)*EMB+tid] - sai[cur][e+2]*P[(e+2)*EMB+tid];
                a3 += sar[cur][e+3]*K[(e+3)*EMB+tid] - sai[cur][e+3]*P[(e+3)*EMB+tid];
            }
            a0 += sar[cur][48]*K[48*EMB+tid] - sai[cur][48]*P[48*EMB+tid];
            a1 += sar[cur][49]*K[49*EMB+tid] - sai[cur][49]*P[49*EMB+tid];
            sar[nxt][tid] = (a0+a1) + (a2+a3);
        } else if (tid >= 64 && tid < 64 + EMB) {  // imag, f = tid-64
            const int f = tid - 64;
            float a0=0.f,a1=0.f,a2=0.f,a3=0.f;
            #pragma unroll
            for (int e = 0; e < 48; e += 4) {
                a0 += sar[cur][e+0]*P[(e+0)*EMB+f] + sai[cur][e+0]*K[(e+0)*EMB+f];
                a1 += sar[cur][e+1]*P[(e+1)*EMB+f] + sai[cur][e+1]*K[(e+1)*EMB+f];
                a2 += sar[cur][e+2]*P[(e+2)*EMB+f] + sai[cur][e+2]*K[(e+2)*EMB+f];
                a3 += sar[cur][e+3]*P[(e+3)*EMB+f] + sai[cur][e+3]*K[(e+3)*EMB+f];
            }
            a0 += sar[cur][48]*P[48*EMB+f] + sai[cur][48]*K[48*EMB+f];
            a1 += sar[cur][49]*P[49*EMB+f] + sai[cur][49]*K[49*EMB+f];
            sai[nxt][f] = (a0+a1) + (a2+a3);
        }
        __syncthreads();
    }

    // 8 layers (even): result in buffer index 0
    if (tid < EMB) {
        float a = sar[0][tid], b = sai[0][tid];
        sint[tid] = a*a + b*b;
    }
    __syncthreads();
    if (tid < VOCAB) {
        float acc = __ldg(b_out + tid);
        #pragma unroll
        for (int e = 0; e < EMB; ++e)
            acc += sint[e] * __ldg(W_out + e*VOCAB + tid);
        // 4 shifted replicas (pads: j=0->0, 1->3, 2->2, 3->1)
        g_tab[0*REP_FLOATS + t*72 + tid + 0] = acc;
        g_tab[1*REP_FLOATS + t*72 + tid + 3] = acc;
        g_tab[2*REP_FLOATS + t*72 + tid + 2] = acc;
        g_tab[3*REP_FLOATS + t*72 + tid + 1] = acc;
    }
}

// ---------------------------------------------------------------------------
// Kernel 2: gather. One warp = 32 consecutive tokens = 2144 floats = 536
// float4s (exact). Lane owns output float4 p4 = lane + 32*i -> STG.128 is
// 512B contiguous, 128B-aligned per warp. Token id for p4 fetched by shfl.
// Main table read = one aligned LDG.128 from the matching shifted replica;
// token-boundary straddles (r>=64) take one predicated fixup LDG.
// ---------------------------------------------------------------------------
__device__ __forceinline__ void stcs128(float4* p, float4 v) {
    asm volatile("st.global.cs.v4.f32 [%0], {%1,%2,%3,%4};"
                 :: "l"(p), "f"(v.x), "f"(v.y), "f"(v.z), "f"(v.w) : "memory");
}

__global__ void __launch_bounds__(256) gather_kernel(
    const int* __restrict__ idx, float* __restrict__ out)
{
    const int lane = threadIdx.x & 31;
    const int warp = (blockIdx.x * 256 + (int)threadIdx.x) >> 5;   // 0..16383

    const int mytok = __ldg(idx + warp*32 + lane);   // this lane's token id
    float4* O = (float4*)out + (uint32_t)warp * 536;

    #pragma unroll
    for (int i = 0; i < 17; ++i) {
        const int p4 = lane + 32*i;          // output float4 index (may be >=536 on i=16)
        const int e0 = 4*p4;
        const int tk = e0 / 67;              // owning token slot (0..31 valid)
        const int r  = e0 - 67*tk;           // element offset within token row

        const int token  = __shfl_sync(0xffffffffu, mytok, tk < 31 ? tk : 31);
        const int token2 = __shfl_sync(0xffffffffu, mytok, tk < 30 ? tk+1 : 31);

        const int j   = r & 3;
        const int pos = (r + 3) & ~3;        // r + pad_j, 16B-aligned
        float4 v = __ldg((const float4*)(g_tab + j*REP_FLOATS + token*72 + pos));

        if (r >= 64) {                       // straddle: tail from next token
            float4 w = __ldg((const float4*)(g_tab + (j+1)*REP_FLOATS + token2*72));
            if (r == 66) v.y = w.y;
            if (r >= 65) v.z = w.z;
            v.w = w.w;
        }
        if (p4 < 536) stcs128(O + p4, v);
    }
}

// ---------------------------------------------------------------------------
// Launch
// ---------------------------------------------------------------------------
extern "C" void kernel_launch(void* const* d_in, const int* in_sizes, int n_in,
                              void* d_out, int out_size) {
    const int*   idx = (const int*)d_in[0];   // input_seq [64,8192] int32
    const float* emb = (const float*)d_in[1]; // embedding_table [67,50]
    const float* kap = (const float*)d_in[2]; // kappa [8,50,50]
    const float* ph  = (const float*)d_in[3]; // phi   [8,50,50]
    const float* Wo  = (const float*)d_in[4]; // W_out [50,67]
    const float* bo  = (const float*)d_in[5]; // b_out [67]
    float* out = (float*)d_out;

    table_kernel<<<VOCAB, 128>>>(emb, kap, ph, Wo, bo);
    gather_kernel<<<2048, 256>>>(idx, out);   // 16384 warps, 32 tokens each
}